// round 14
// baseline (speedup 1.0000x reference)
#include <cuda_runtime.h>

#define NBLK 1184   // 148 SMs x 8 blocks: one wave
#define NTHR 256
#define BIG4 2048   // big chunk: 2048 float4 = 32KB per array (row-buffer runs)
#define SML4 512    // small chunk: 512 float4 = 8KB per array (tail smoothing)
// Guided scheduling: 32KB chunks for the bulk (locality, low steal overhead),
// then ~2 small 8KB chunks per block at the end so finish skew <= ~0.7us.
// Homogeneous sweep measured: 8KB=46.85us, 16KB=45.79us, 32KB=48.03us (tail).

// Device scratch (no cudaMalloc allowed). Both counters self-reset:
//  - g_chunk: exactly (nbig+nsml) + NBLK atomicInc per launch (each block
//    consumes exactly one stop ticket); wrap returns it to 0 every launch.
//  - g_count: wraps at NBLK.
__device__ unsigned int g_chunk;
__device__ float g_part[NBLK];
__device__ unsigned int g_count;

__global__ void __launch_bounds__(NTHR)
mse_kernel(const float* __restrict__ in,
           const float* __restrict__ tg,
           float* __restrict__ out,
           int n) {
    const float4* __restrict__ in4 = (const float4*)in;
    const float4* __restrict__ tg4 = (const float4*)tg;
    const int n4 = n >> 2;

    // Partition: big region first, then >=2*NBLK small chunks (if work allows).
    int nbig = (n4 - 2 * NBLK * SML4) / BIG4;
    if (nbig < 0) nbig = 0;
    const int small_base = nbig * BIG4;
    const int nsml = (n4 - small_base + SML4 - 1) / SML4;
    const unsigned total = (unsigned)(nbig + nsml);
    const unsigned wrapv = total + NBLK - 1;   // atomicInc wrap boundary

    __shared__ unsigned s_next[2];
    float acc0 = 0.0f, acc1 = 0.0f;

    if (threadIdx.x == 0) s_next[0] = atomicInc(&g_chunk, wrapv);
    __syncthreads();
    unsigned cur = s_next[0];
    int buf = 1;

    while (cur < total) {
        if (threadIdx.x == 0) s_next[buf] = atomicInc(&g_chunk, wrapv);

        if ((int)cur < nbig) {
            // ── Big 32KB chunk: 8 sequential sub-trips, always in-bounds ──
            int base = (int)cur * BIG4 + threadIdx.x;
            #pragma unroll
            for (int t = 0; t < 8; t += 2) {
                int i0 = base + t * NTHR;
                int i1 = base + (t + 1) * NTHR;
                float4 a0 = __ldg(&in4[i0]);
                float4 a1 = __ldg(&in4[i1]);
                float4 b0 = __ldg(&tg4[i0]);
                float4 b1 = __ldg(&tg4[i1]);
                float d;
                d = a0.x - b0.x; acc0 = fmaf(d, d, acc0);
                d = a0.y - b0.y; acc1 = fmaf(d, d, acc1);
                d = a0.z - b0.z; acc0 = fmaf(d, d, acc0);
                d = a0.w - b0.w; acc1 = fmaf(d, d, acc1);
                d = a1.x - b1.x; acc0 = fmaf(d, d, acc0);
                d = a1.y - b1.y; acc1 = fmaf(d, d, acc1);
                d = a1.z - b1.z; acc0 = fmaf(d, d, acc0);
                d = a1.w - b1.w; acc1 = fmaf(d, d, acc1);
            }
        } else {
            // ── Small 8KB chunk: 2 sub-trips, bounds-checked tail ──
            int base = small_base + ((int)cur - nbig) * SML4 + threadIdx.x;
            if (base + NTHR < n4) {  // full small chunk
                int i0 = base;
                int i1 = base + NTHR;
                float4 a0 = __ldg(&in4[i0]);
                float4 a1 = __ldg(&in4[i1]);
                float4 b0 = __ldg(&tg4[i0]);
                float4 b1 = __ldg(&tg4[i1]);
                float d;
                d = a0.x - b0.x; acc0 = fmaf(d, d, acc0);
                d = a0.y - b0.y; acc1 = fmaf(d, d, acc1);
                d = a0.z - b0.z; acc0 = fmaf(d, d, acc0);
                d = a0.w - b0.w; acc1 = fmaf(d, d, acc1);
                d = a1.x - b1.x; acc0 = fmaf(d, d, acc0);
                d = a1.y - b1.y; acc1 = fmaf(d, d, acc1);
                d = a1.z - b1.z; acc0 = fmaf(d, d, acc0);
                d = a1.w - b1.w; acc1 = fmaf(d, d, acc1);
            } else {  // partial final chunk
                for (int i = base; i < n4; i += NTHR) {
                    float4 a = __ldg(&in4[i]);
                    float4 b = __ldg(&tg4[i]);
                    float d;
                    d = a.x - b.x; acc0 = fmaf(d, d, acc0);
                    d = a.y - b.y; acc1 = fmaf(d, d, acc1);
                    d = a.z - b.z; acc0 = fmaf(d, d, acc0);
                    d = a.w - b.w; acc1 = fmaf(d, d, acc1);
                }
            }
        }

        __syncthreads();   // s_next[buf] now valid for everyone
        cur = s_next[buf];
        buf ^= 1;
    }

    float acc = acc0 + acc1;

    // Warp reduction
    #pragma unroll
    for (int off = 16; off > 0; off >>= 1)
        acc += __shfl_xor_sync(0xFFFFFFFFu, acc, off);

    __shared__ float warp_sums[NTHR / 32];
    int lane = threadIdx.x & 31;
    int wid  = threadIdx.x >> 5;
    if (lane == 0) warp_sums[wid] = acc;
    __syncthreads();

    __shared__ bool is_last;
    if (wid == 0) {
        float v = (lane < NTHR / 32) ? warp_sums[lane] : 0.0f;
        #pragma unroll
        for (int off = 16; off > 0; off >>= 1)
            v += __shfl_xor_sync(0xFFFFFFFFu, v, off);
        if (lane == 0) {
            g_part[blockIdx.x] = v;
            __threadfence();
            unsigned old = atomicInc(&g_count, NBLK - 1);  // wraps -> replay-safe
            is_last = (old == NBLK - 1);
        }
    }
    __syncthreads();

    if (!is_last) return;

    // ── Last block: reduce the 1184 partials in double + finalize ──
    __threadfence();  // acquire: make all blocks' g_part writes visible

    double s = 0.0;
    for (int k = threadIdx.x; k < NBLK; k += NTHR)
        s += (double)g_part[k];

    #pragma unroll
    for (int off = 16; off > 0; off >>= 1)
        s += __shfl_xor_sync(0xFFFFFFFFu, s, off);

    __shared__ double dsums[NTHR / 32];
    if (lane == 0) dsums[wid] = s;
    __syncthreads();

    if (threadIdx.x == 0) {
        double total_d = 0.0;
        #pragma unroll
        for (int w = 0; w < NTHR / 32; w++) total_d += dsums[w];

        // Element-0 conditional rescale, applied analytically.
        float d0 = fabsf(in[0] - tg[0]);
        bool hit = (d0 == 3.0f) || (d0 == 4.0f) || (d0 == 5.0f) || (d0 == 6.0f);
        float d0a = hit ? d0 * 0.8f : d0;
        total_d += (double)d0a * (double)d0a - (double)d0 * (double)d0;

        out[0] = (float)(total_d / (double)n);
    }
}

extern "C" void kernel_launch(void* const* d_in, const int* in_sizes, int n_in,
                              void* d_out, int out_size) {
    const float* in = (const float*)d_in[0];
    const float* tg = (const float*)d_in[1];
    float* out = (float*)d_out;
    int n = in_sizes[0];

    mse_kernel<<<NBLK, NTHR>>>(in, tg, out, n);
}

// round 16
// speedup vs baseline: 1.0318x; 1.0318x over previous
#include <cuda_runtime.h>

#define NBLK 1184   // 148 SMs x 8 blocks: one wave
#define NTHR 256
#define TRIPS 4                  // sequential 4KB sub-trips per chunk
#define CHUNK4 (TRIPS * NTHR)    // 1024 float4 = 16KB per array per chunk
// Chunk-size sweep (ncu kernel dur): 8KB=46.85us, 16KB=45.79/45.98us (x2),
// 32KB=48.03us, guided 32KB+8KB-tail=48.19us. 16KB is a two-sided optimum:
// long enough for DRAM row-buffer runs, fine enough to keep many concurrent
// streams per channel. This is the final configuration.

// Device scratch (no cudaMalloc allowed). Both counters self-reset:
//  - g_chunk: exactly NCHUNK + NBLK atomicInc per launch (each block consumes
//    exactly one stop ticket), wrap value makes it return to 0 every launch.
//  - g_count: wraps at NBLK.
__device__ unsigned int g_chunk;
__device__ float g_part[NBLK];
__device__ unsigned int g_count;

__global__ void __launch_bounds__(NTHR)
mse_kernel(const float* __restrict__ in,
           const float* __restrict__ tg,
           float* __restrict__ out,
           int n) {
    const float4* __restrict__ in4 = (const float4*)in;
    const float4* __restrict__ tg4 = (const float4*)tg;
    const int n4 = n >> 2;

    const unsigned nchunk = (unsigned)((n4 + CHUNK4 - 1) / CHUNK4);
    const unsigned wrapv  = nchunk + NBLK - 1;  // atomicInc wrap boundary

    __shared__ unsigned s_next[2];
    float acc0 = 0.0f, acc1 = 0.0f;

    // Dynamic work-stealing over 16KB-per-array chunks. Double-buffered id
    // prefetch hides the atomic latency behind the chunk's loads.
    if (threadIdx.x == 0) s_next[0] = atomicInc(&g_chunk, wrapv);
    __syncthreads();
    unsigned cur = s_next[0];
    int buf = 1;

    while (cur < nchunk) {
        if (threadIdx.x == 0) s_next[buf] = atomicInc(&g_chunk, wrapv);

        int base = (int)cur * CHUNK4 + threadIdx.x;
        if (base + (TRIPS - 1) * NTHR < n4) {  // full chunk (common case)
            #pragma unroll
            for (int t = 0; t < TRIPS; t += 2) {
                int i0 = base + t * NTHR;
                int i1 = base + (t + 1) * NTHR;
                float4 a0 = __ldg(&in4[i0]);
                float4 a1 = __ldg(&in4[i1]);
                float4 b0 = __ldg(&tg4[i0]);
                float4 b1 = __ldg(&tg4[i1]);
                float d;
                d = a0.x - b0.x; acc0 = fmaf(d, d, acc0);
                d = a0.y - b0.y; acc1 = fmaf(d, d, acc1);
                d = a0.z - b0.z; acc0 = fmaf(d, d, acc0);
                d = a0.w - b0.w; acc1 = fmaf(d, d, acc1);
                d = a1.x - b1.x; acc0 = fmaf(d, d, acc0);
                d = a1.y - b1.y; acc1 = fmaf(d, d, acc1);
                d = a1.z - b1.z; acc0 = fmaf(d, d, acc0);
                d = a1.w - b1.w; acc1 = fmaf(d, d, acc1);
            }
        } else {  // partial tail chunk
            for (int i = base; i < n4; i += NTHR) {
                float4 a = __ldg(&in4[i]);
                float4 b = __ldg(&tg4[i]);
                float d;
                d = a.x - b.x; acc0 = fmaf(d, d, acc0);
                d = a.y - b.y; acc1 = fmaf(d, d, acc1);
                d = a.z - b.z; acc0 = fmaf(d, d, acc0);
                d = a.w - b.w; acc1 = fmaf(d, d, acc1);
            }
        }

        __syncthreads();   // s_next[buf] now valid for everyone
        cur = s_next[buf];
        buf ^= 1;
    }

    float acc = acc0 + acc1;

    // Warp reduction
    #pragma unroll
    for (int off = 16; off > 0; off >>= 1)
        acc += __shfl_xor_sync(0xFFFFFFFFu, acc, off);

    __shared__ float warp_sums[NTHR / 32];
    int lane = threadIdx.x & 31;
    int wid  = threadIdx.x >> 5;
    if (lane == 0) warp_sums[wid] = acc;
    __syncthreads();

    __shared__ bool is_last;
    if (wid == 0) {
        float v = (lane < NTHR / 32) ? warp_sums[lane] : 0.0f;
        #pragma unroll
        for (int off = 16; off > 0; off >>= 1)
            v += __shfl_xor_sync(0xFFFFFFFFu, v, off);
        if (lane == 0) {
            g_part[blockIdx.x] = v;
            __threadfence();
            unsigned old = atomicInc(&g_count, NBLK - 1);  // wraps -> replay-safe
            is_last = (old == NBLK - 1);
        }
    }
    __syncthreads();

    if (!is_last) return;

    // ── Last block: reduce the 1184 partials in double + finalize ──
    __threadfence();  // acquire: make all blocks' g_part writes visible

    double s = 0.0;
    for (int k = threadIdx.x; k < NBLK; k += NTHR)
        s += (double)g_part[k];

    #pragma unroll
    for (int off = 16; off > 0; off >>= 1)
        s += __shfl_xor_sync(0xFFFFFFFFu, s, off);

    __shared__ double dsums[NTHR / 32];
    if (lane == 0) dsums[wid] = s;
    __syncthreads();

    if (threadIdx.x == 0) {
        double total = 0.0;
        #pragma unroll
        for (int w = 0; w < NTHR / 32; w++) total += dsums[w];

        // Element-0 conditional rescale, applied analytically.
        float d0 = fabsf(in[0] - tg[0]);
        bool hit = (d0 == 3.0f) || (d0 == 4.0f) || (d0 == 5.0f) || (d0 == 6.0f);
        float d0a = hit ? d0 * 0.8f : d0;
        total += (double)d0a * (double)d0a - (double)d0 * (double)d0;

        out[0] = (float)(total / (double)n);
    }
}

extern "C" void kernel_launch(void* const* d_in, const int* in_sizes, int n_in,
                              void* d_out, int out_size) {
    const float* in = (const float*)d_in[0];
    const float* tg = (const float*)d_in[1];
    float* out = (float*)d_out;
    int n = in_sizes[0];

    mse_kernel<<<NBLK, NTHR>>>(in, tg, out, n);
}

// round 17
// speedup vs baseline: 1.0554x; 1.0229x over previous
#include <cuda_runtime.h>

#define NBLK 1184   // 148 SMs x 8 blocks: one wave
#define NTHR 256
#define TRIPS 4                  // sequential 4KB sub-trips per chunk
#define CHUNK4 (TRIPS * NTHR)    // 1024 float4 = 16KB per array per chunk
// FINAL. Campaign summary (ncu kernel dur, noise band +-1.5us on same code):
//   16KB steal: 45.79 / 45.98 / 47.46 (best recorded config, 3 runs)
//   8KB steal 46.85, grid-stride 45.95, unroll variants ~46.8 (all in-band)
//   32KB 48.03, guided 48.19, TMA pipeline 48.16, 4096-block grid 51.9-55.8
// Chip ceiling for this 2-stream read: ~5.8-5.95 TB/s (~74% of 8TB/s spec),
// path-independent (LDG == TMA). 256MiB / 5.9TB/s = ~45.5us = measured floor.

// Device scratch (no cudaMalloc allowed). Both counters self-reset:
//  - g_chunk: exactly NCHUNK + NBLK atomicInc per launch (each block consumes
//    exactly one stop ticket), wrap value makes it return to 0 every launch.
//  - g_count: wraps at NBLK.
__device__ unsigned int g_chunk;
__device__ float g_part[NBLK];
__device__ unsigned int g_count;

__global__ void __launch_bounds__(NTHR)
mse_kernel(const float* __restrict__ in,
           const float* __restrict__ tg,
           float* __restrict__ out,
           int n) {
    const float4* __restrict__ in4 = (const float4*)in;
    const float4* __restrict__ tg4 = (const float4*)tg;
    const int n4 = n >> 2;

    const unsigned nchunk = (unsigned)((n4 + CHUNK4 - 1) / CHUNK4);
    const unsigned wrapv  = nchunk + NBLK - 1;  // atomicInc wrap boundary

    __shared__ unsigned s_next[2];
    float acc0 = 0.0f, acc1 = 0.0f;

    // Dynamic work-stealing over 16KB-per-array chunks. Double-buffered id
    // prefetch hides the atomic latency behind the chunk's loads.
    if (threadIdx.x == 0) s_next[0] = atomicInc(&g_chunk, wrapv);
    __syncthreads();
    unsigned cur = s_next[0];
    int buf = 1;

    while (cur < nchunk) {
        if (threadIdx.x == 0) s_next[buf] = atomicInc(&g_chunk, wrapv);

        int base = (int)cur * CHUNK4 + threadIdx.x;
        if (base + (TRIPS - 1) * NTHR < n4) {  // full chunk (common case)
            #pragma unroll
            for (int t = 0; t < TRIPS; t += 2) {
                int i0 = base + t * NTHR;
                int i1 = base + (t + 1) * NTHR;
                float4 a0 = __ldg(&in4[i0]);
                float4 a1 = __ldg(&in4[i1]);
                float4 b0 = __ldg(&tg4[i0]);
                float4 b1 = __ldg(&tg4[i1]);
                float d;
                d = a0.x - b0.x; acc0 = fmaf(d, d, acc0);
                d = a0.y - b0.y; acc1 = fmaf(d, d, acc1);
                d = a0.z - b0.z; acc0 = fmaf(d, d, acc0);
                d = a0.w - b0.w; acc1 = fmaf(d, d, acc1);
                d = a1.x - b1.x; acc0 = fmaf(d, d, acc0);
                d = a1.y - b1.y; acc1 = fmaf(d, d, acc1);
                d = a1.z - b1.z; acc0 = fmaf(d, d, acc0);
                d = a1.w - b1.w; acc1 = fmaf(d, d, acc1);
            }
        } else {  // partial tail chunk
            for (int i = base; i < n4; i += NTHR) {
                float4 a = __ldg(&in4[i]);
                float4 b = __ldg(&tg4[i]);
                float d;
                d = a.x - b.x; acc0 = fmaf(d, d, acc0);
                d = a.y - b.y; acc1 = fmaf(d, d, acc1);
                d = a.z - b.z; acc0 = fmaf(d, d, acc0);
                d = a.w - b.w; acc1 = fmaf(d, d, acc1);
            }
        }

        __syncthreads();   // s_next[buf] now valid for everyone
        cur = s_next[buf];
        buf ^= 1;
    }

    float acc = acc0 + acc1;

    // Warp reduction
    #pragma unroll
    for (int off = 16; off > 0; off >>= 1)
        acc += __shfl_xor_sync(0xFFFFFFFFu, acc, off);

    __shared__ float warp_sums[NTHR / 32];
    int lane = threadIdx.x & 31;
    int wid  = threadIdx.x >> 5;
    if (lane == 0) warp_sums[wid] = acc;
    __syncthreads();

    __shared__ bool is_last;
    if (wid == 0) {
        float v = (lane < NTHR / 32) ? warp_sums[lane] : 0.0f;
        #pragma unroll
        for (int off = 16; off > 0; off >>= 1)
            v += __shfl_xor_sync(0xFFFFFFFFu, v, off);
        if (lane == 0) {
            g_part[blockIdx.x] = v;
            __threadfence();
            unsigned old = atomicInc(&g_count, NBLK - 1);  // wraps -> replay-safe
            is_last = (old == NBLK - 1);
        }
    }
    __syncthreads();

    if (!is_last) return;

    // ── Last block: reduce the 1184 partials in double + finalize ──
    __threadfence();  // acquire: make all blocks' g_part writes visible

    double s = 0.0;
    for (int k = threadIdx.x; k < NBLK; k += NTHR)
        s += (double)g_part[k];

    #pragma unroll
    for (int off = 16; off > 0; off >>= 1)
        s += __shfl_xor_sync(0xFFFFFFFFu, s, off);

    __shared__ double dsums[NTHR / 32];
    if (lane == 0) dsums[wid] = s;
    __syncthreads();

    if (threadIdx.x == 0) {
        double total = 0.0;
        #pragma unroll
        for (int w = 0; w < NTHR / 32; w++) total += dsums[w];

        // Element-0 conditional rescale, applied analytically.
        float d0 = fabsf(in[0] - tg[0]);
        bool hit = (d0 == 3.0f) || (d0 == 4.0f) || (d0 == 5.0f) || (d0 == 6.0f);
        float d0a = hit ? d0 * 0.8f : d0;
        total += (double)d0a * (double)d0a - (double)d0 * (double)d0;

        out[0] = (float)(total / (double)n);
    }
}

extern "C" void kernel_launch(void* const* d_in, const int* in_sizes, int n_in,
                              void* d_out, int out_size) {
    const float* in = (const float*)d_in[0];
    const float* tg = (const float*)d_in[1];
    float* out = (float*)d_out;
    int n = in_sizes[0];

    mse_kernel<<<NBLK, NTHR>>>(in, tg, out, n);
}